// round 3
// baseline (speedup 1.0000x reference)
#include <cuda_runtime.h>
#include <math.h>

#define NN 262144
#define NE 1048576
#define NG 8192
#define EPG 128

// ---------------- scratch (sanctioned __device__ globals) ----------------
__device__ float g_A[NG * 1024];                     // per-graph 32x32 normalized adjacency
__device__ float g_bufA[(size_t)NN * 312];           // XW intermediate
__device__ float g_bufB[(size_t)NN * 312];           // H (post-prop) intermediate
__device__ float g_pool[NG * 312];
__device__ float g_t512[NG * 512];
__device__ float g_t256[NG * 256];
__device__ float g_g1[NG * 128];
__device__ float g_g2[NG * 128];
__device__ float g_cell[NG * 128];
__device__ float g_xc[NG * 384];

// ---------------- build per-graph normalized adjacency ----------------
// A[r][c] = dinv[r]*dinv[c] * (multiplicity of edge (r,c)) + self-loop on diagonal
// deg[r] = #edges with row==r (+1 self loop); dinv = rsqrt(deg)
__global__ void build_A_kernel(const int* __restrict__ ei, float* __restrict__ A) {
    __shared__ int   deg[32];
    __shared__ float dinv[32];
    __shared__ float cnt[1024];
    int g = blockIdx.x, t = threadIdx.x;            // 128 threads, exactly 1 edge each
    if (t < 32) deg[t] = 1;                          // self loop
    for (int i = t; i < 1024; i += 128) cnt[i] = 0.f;
    __syncthreads();
    int src = ei[g * EPG + t] & 31;                  // row (local: graph offset is g*32)
    int dst = ei[NE + g * EPG + t] & 31;             // col
    atomicAdd(&deg[src], 1);
    __syncthreads();
    if (t < 32) dinv[t] = rsqrtf((float)deg[t]);
    atomicAdd(&cnt[src * 32 + dst], 1.f);
    __syncthreads();
    for (int i = t; i < 1024; i += 128) {
        int r = i >> 5, c = i & 31;
        float v = cnt[i] + (r == c ? 1.f : 0.f);
        A[g * 1024 + i] = v * dinv[r] * dinv[c];
    }
}

// ---------------- generic tiled GEMM: C = act(X @ W + bias) ----------------
// X: N x K row-major, W: K x M row-major, C: N x M row-major
// ACT: 0 none, 1 relu, 2 prelu(alpha from device scalar)
#define BM 64
#define BN 64
#define BK 16

template <int ACT>
__global__ void gemm_kernel(const float* __restrict__ X, const float* __restrict__ W,
                            const float* __restrict__ bias, float* __restrict__ C,
                            int N, int K, int M, const float* __restrict__ pa) {
    __shared__ float As[BK][BM + 4];   // +4 pad: keeps 16B alignment, kills store conflicts
    __shared__ float Bs[BK][BN];
    int tid = threadIdx.x;
    int tx = tid & 15, ty = tid >> 4;
    int n0 = blockIdx.y * BM;
    int m0 = blockIdx.x * BN;
    float acc[4][4] = {};
    for (int k0 = 0; k0 < K; k0 += BK) {
#pragma unroll
        for (int i = 0; i < 4; i++) {                // load X tile (transposed into As)
            int idx = tid + i * 256;                 // 0..1023
            int r = idx >> 4, kk = idx & 15;
            int row = n0 + r, k = k0 + kk;
            As[kk][r] = (row < N && k < K) ? X[(size_t)row * K + k] : 0.f;
        }
#pragma unroll
        for (int i = 0; i < 4; i++) {                // load W tile
            int idx = tid + i * 256;
            int kk = idx >> 6, m = idx & 63;
            int k = k0 + kk, col = m0 + m;
            Bs[kk][m] = (k < K && col < M) ? W[(size_t)k * M + col] : 0.f;
        }
        __syncthreads();
#pragma unroll
        for (int kk = 0; kk < BK; kk++) {
            float a[4], b[4];
#pragma unroll
            for (int i = 0; i < 4; i++) a[i] = As[kk][ty * 4 + i];
#pragma unroll
            for (int j = 0; j < 4; j++) b[j] = Bs[kk][tx * 4 + j];
#pragma unroll
            for (int i = 0; i < 4; i++)
#pragma unroll
                for (int j = 0; j < 4; j++) acc[i][j] = fmaf(a[i], b[j], acc[i][j]);
        }
        __syncthreads();
    }
    float alpha = 0.f;
    if (ACT == 2) alpha = *pa;
#pragma unroll
    for (int i = 0; i < 4; i++) {
        int row = n0 + ty * 4 + i;
        if (row >= N) continue;
#pragma unroll
        for (int j = 0; j < 4; j++) {
            int col = m0 + tx * 4 + j;
            if (col >= M) continue;
            float v = acc[i][j] + (bias ? bias[col] : 0.f);
            if (ACT == 1) v = fmaxf(v, 0.f);
            if (ACT == 2) v = (v >= 0.f) ? v : alpha * v;
            C[(size_t)row * M + col] = v;
        }
    }
}

// ---------------- propagation: H = relu(A_g @ T_g + b), per graph ----------------
__global__ void prop_kernel(const float* __restrict__ A, const float* __restrict__ T,
                            const float* __restrict__ bias, float* __restrict__ out, int F) {
    __shared__ float sA[1024];
    __shared__ float sT[32 * 312];
    int g = blockIdx.x;
    const float* Ag = A + g * 1024;
    const float* Tg = T + (size_t)g * 32 * F;
    for (int i = threadIdx.x; i < 1024; i += 256) sA[i] = Ag[i];
    int tot = 32 * F;
    for (int i = threadIdx.x; i < tot; i += 256) sT[i] = Tg[i];
    __syncthreads();
    for (int idx = threadIdx.x; idx < tot; idx += 256) {
        int r = idx / F, f = idx - r * F;
        float acc = bias[f];
        const float* Ar = sA + r * 32;
#pragma unroll
        for (int c = 0; c < 32; c++) acc = fmaf(Ar[c], sT[c * F + f], acc);
        out[(size_t)(g * 32 + r) * F + f] = fmaxf(acc, 0.f);
    }
}

// ---------------- global max pool over 32 nodes per graph ----------------
__global__ void pool_kernel(const float* __restrict__ H, float* __restrict__ out, int F) {
    int g = blockIdx.x, f = threadIdx.x;
    if (f >= F) return;
    const float* Hg = H + (size_t)g * 32 * F;
    float m = -3.4e38f;
#pragma unroll
    for (int r = 0; r < 32; r++) m = fmaxf(m, Hg[r * F + f]);
    out[g * F + f] = m;
}

// ---------------- concat [g1,g2,c] + L2 normalize row ----------------
__global__ void catnorm_kernel(const float* __restrict__ g1, const float* __restrict__ g2,
                               const float* __restrict__ c, float* __restrict__ xc) {
    int g = blockIdx.x, t = threadIdx.x;   // 128 threads
    float v0 = g1[g * 128 + t], v1 = g2[g * 128 + t], v2 = c[g * 128 + t];
    float ps = v0 * v0 + v1 * v1 + v2 * v2;
    __shared__ float red[4];
#pragma unroll
    for (int o = 16; o; o >>= 1) ps += __shfl_xor_sync(0xffffffffu, ps, o);
    if ((t & 31) == 0) red[t >> 5] = ps;
    __syncthreads();
    float tot = red[0] + red[1] + red[2] + red[3];
    float inv = 1.f / fmaxf(sqrtf(tot), 1e-12f);
    xc[g * 384 + t]       = v0 * inv;
    xc[g * 384 + 128 + t] = v1 * inv;
    xc[g * 384 + 256 + t] = v2 * inv;
}

// ---------------- final: sigmoid(x @ Wo + bo), one warp per row ----------------
__global__ void final_kernel(const float* __restrict__ x, const float* __restrict__ Wo,
                             const float* __restrict__ bo, float* __restrict__ out) {
    int w = (blockIdx.x * blockDim.x + threadIdx.x) >> 5;
    int lane = threadIdx.x & 31;
    if (w >= NG) return;
    float acc = 0.f;
#pragma unroll
    for (int k = lane; k < 128; k += 32) acc = fmaf(x[w * 128 + k], Wo[k], acc);
#pragma unroll
    for (int o = 16; o; o >>= 1) acc += __shfl_xor_sync(0xffffffffu, acc, o);
    if (lane == 0) out[w] = 1.f / (1.f + expf(-(acc + bo[0])));
}

// ---------------- host side ----------------
static void gemm_launch(const float* X, const float* W, const float* bias, float* C,
                        int N, int K, int M, int act, const float* pa) {
    dim3 grid((M + BN - 1) / BN, (N + BM - 1) / BM);
    if (act == 0)      gemm_kernel<0><<<grid, 256>>>(X, W, bias, C, N, K, M, nullptr);
    else if (act == 1) gemm_kernel<1><<<grid, 256>>>(X, W, bias, C, N, K, M, nullptr);
    else               gemm_kernel<2><<<grid, 256>>>(X, W, bias, C, N, K, M, pa);
}

extern "C" void kernel_launch(void* const* d_in, const int* in_sizes, int n_in,
                              void* d_out, int out_size) {
    const float* x1   = (const float*)d_in[0];
    const int*   ei1  = (const int*)d_in[1];
    const float* x2   = (const float*)d_in[2];
    const int*   ei2  = (const int*)d_in[3];
    const float* cell = (const float*)d_in[4];
    // d_in[5], d_in[6]: batch vectors (implied by node index; unused)
    const float* W1  = (const float*)d_in[7],  *b1  = (const float*)d_in[8];
    const float* W2  = (const float*)d_in[9],  *b2  = (const float*)d_in[10];
    const float* W3  = (const float*)d_in[11], *b3  = (const float*)d_in[12];
    const float* Wg1 = (const float*)d_in[13], *bg1 = (const float*)d_in[14];
    const float* Wg2 = (const float*)d_in[15], *bg2 = (const float*)d_in[16];
    const float* Wr1 = (const float*)d_in[17], *br1 = (const float*)d_in[18];
    const float* Wr2 = (const float*)d_in[19], *br2 = (const float*)d_in[20];
    const float* Wr3 = (const float*)d_in[21], *br3 = (const float*)d_in[22];
    const float* Wf1 = (const float*)d_in[23], *bf1 = (const float*)d_in[24];
    const float* Wf2 = (const float*)d_in[25], *bf2 = (const float*)d_in[26];
    const float* Wo  = (const float*)d_in[27], *bo  = (const float*)d_in[28];
    const float* pa  = (const float*)d_in[29];
    float* out = (float*)d_out;

    float *A, *bufA, *bufB, *pool, *t512, *t256, *G1, *G2, *Cl, *XC;
    cudaGetSymbolAddress((void**)&A,    g_A);
    cudaGetSymbolAddress((void**)&bufA, g_bufA);
    cudaGetSymbolAddress((void**)&bufB, g_bufB);
    cudaGetSymbolAddress((void**)&pool, g_pool);
    cudaGetSymbolAddress((void**)&t512, g_t512);
    cudaGetSymbolAddress((void**)&t256, g_t256);
    cudaGetSymbolAddress((void**)&G1,   g_g1);
    cudaGetSymbolAddress((void**)&G2,   g_g2);
    cudaGetSymbolAddress((void**)&Cl,   g_cell);
    cudaGetSymbolAddress((void**)&XC,   g_xc);

    for (int d = 0; d < 2; d++) {
        const float* x  = d ? x2 : x1;
        const int*   ei = d ? ei2 : ei1;
        float*       G  = d ? G2 : G1;
        build_A_kernel<<<NG, 128>>>(ei, A);
        // layer 1: relu(A @ (x W1) + b1)
        gemm_launch(x, W1, nullptr, bufA, NN, 78, 78, 0, pa);
        prop_kernel<<<NG, 256>>>(A, bufA, b1, bufB, 78);
        // layer 2
        gemm_launch(bufB, W2, nullptr, bufA, NN, 78, 156, 0, pa);
        prop_kernel<<<NG, 256>>>(A, bufA, b2, bufB, 156);
        // layer 3
        gemm_launch(bufB, W3, nullptr, bufA, NN, 156, 312, 0, pa);
        prop_kernel<<<NG, 256>>>(A, bufA, b3, bufB, 312);
        // global max pool + FC head of drug branch
        pool_kernel<<<NG, 320>>>(bufB, pool, 312);
        gemm_launch(pool, Wg1, bg1, t512, NG, 312, 156, 1, pa);
        gemm_launch(t512, Wg2, bg2, G,    NG, 156, 128, 0, pa);
    }

    // cell-line MLP
    gemm_launch(cell, Wr1, br1, t512, NG, 1000, 512, 1, pa);
    gemm_launch(t512, Wr2, br2, t256, NG, 512,  256, 1, pa);
    gemm_launch(t256, Wr3, br3, Cl,   NG, 256,  128, 0, pa);

    // concat + L2 normalize + fused head
    catnorm_kernel<<<NG, 128>>>(G1, G2, Cl, XC);
    gemm_launch(XC,   Wf1, bf1, t512, NG, 384, 512, 2, pa);
    gemm_launch(t512, Wf2, bf2, t256, NG, 512, 128, 2, pa);
    final_kernel<<<NG / 8, 256>>>(t256, Wo, bo, out);
}

// round 5
// speedup vs baseline: 1.0039x; 1.0039x over previous
#include <cuda_runtime.h>
#include <math.h>

#define NN 262144
#define NE 1048576
#define NG 8192
#define EPG 128

// ---------------- scratch (sanctioned __device__ globals) ----------------
__device__ float g_A[NG * 1024];                     // per-graph 32x32 normalized adjacency
__device__ float g_bufA[(size_t)NN * 312];           // XW intermediate
__device__ float g_bufB[(size_t)NN * 312];           // H (post-prop) intermediate
__device__ float g_pool[NG * 312];
__device__ float g_t512[NG * 512];
__device__ float g_t256[NG * 256];
__device__ float g_g1[NG * 128];
__device__ float g_g2[NG * 128];
__device__ float g_cell[NG * 128];
__device__ float g_xc[NG * 384];

// ---------------- build per-graph normalized adjacency ----------------
// A[r][c] = dinv[r]*dinv[c] * (multiplicity of edge (r,c)) + self-loop on diagonal
// deg[r] = #edges with row==r (+1 self loop); dinv = rsqrt(deg)
__global__ void build_A_kernel(const int* __restrict__ ei, float* __restrict__ A) {
    __shared__ int   deg[32];
    __shared__ float dinv[32];
    __shared__ float cnt[1024];
    int g = blockIdx.x, t = threadIdx.x;            // 128 threads, exactly 1 edge each
    if (t < 32) deg[t] = 1;                          // self loop
    for (int i = t; i < 1024; i += 128) cnt[i] = 0.f;
    __syncthreads();
    int src = ei[g * EPG + t] & 31;                  // row (local: graph offset is g*32)
    int dst = ei[NE + g * EPG + t] & 31;             // col
    atomicAdd(&deg[src], 1);
    __syncthreads();
    if (t < 32) dinv[t] = rsqrtf((float)deg[t]);
    atomicAdd(&cnt[src * 32 + dst], 1.f);
    __syncthreads();
    for (int i = t; i < 1024; i += 128) {
        int r = i >> 5, c = i & 31;
        float v = cnt[i] + (r == c ? 1.f : 0.f);
        A[g * 1024 + i] = v * dinv[r] * dinv[c];
    }
}

// ---------------- generic tiled GEMM: C = act(X @ W + bias) ----------------
// X: N x K row-major, W: K x M row-major, C: N x M row-major
// ACT: 0 none, 1 relu, 2 prelu(alpha from device scalar)
#define BM 64
#define BN 64
#define BK 16

template <int ACT>
__global__ void gemm_kernel(const float* __restrict__ X, const float* __restrict__ W,
                            const float* __restrict__ bias, float* __restrict__ C,
                            int N, int K, int M, const float* __restrict__ pa) {
    __shared__ float As[BK][BM + 4];   // +4 pad: keeps 16B alignment, kills store conflicts
    __shared__ float Bs[BK][BN];
    int tid = threadIdx.x;
    int tx = tid & 15, ty = tid >> 4;
    int n0 = blockIdx.y * BM;
    int m0 = blockIdx.x * BN;
    float acc[4][4] = {};
    for (int k0 = 0; k0 < K; k0 += BK) {
#pragma unroll
        for (int i = 0; i < 4; i++) {                // load X tile (transposed into As)
            int idx = tid + i * 256;                 // 0..1023
            int r = idx >> 4, kk = idx & 15;
            int row = n0 + r, k = k0 + kk;
            As[kk][r] = (row < N && k < K) ? X[(size_t)row * K + k] : 0.f;
        }
#pragma unroll
        for (int i = 0; i < 4; i++) {                // load W tile
            int idx = tid + i * 256;
            int kk = idx >> 6, m = idx & 63;
            int k = k0 + kk, col = m0 + m;
            Bs[kk][m] = (k < K && col < M) ? W[(size_t)k * M + col] : 0.f;
        }
        __syncthreads();
#pragma unroll
        for (int kk = 0; kk < BK; kk++) {
            float a[4], b[4];
#pragma unroll
            for (int i = 0; i < 4; i++) a[i] = As[kk][ty * 4 + i];
#pragma unroll
            for (int j = 0; j < 4; j++) b[j] = Bs[kk][tx * 4 + j];
#pragma unroll
            for (int i = 0; i < 4; i++)
#pragma unroll
                for (int j = 0; j < 4; j++) acc[i][j] = fmaf(a[i], b[j], acc[i][j]);
        }
        __syncthreads();
    }
    float alpha = 0.f;
    if (ACT == 2) alpha = *pa;
#pragma unroll
    for (int i = 0; i < 4; i++) {
        int row = n0 + ty * 4 + i;
        if (row >= N) continue;
#pragma unroll
        for (int j = 0; j < 4; j++) {
            int col = m0 + tx * 4 + j;
            if (col >= M) continue;
            float v = acc[i][j] + (bias ? bias[col] : 0.f);
            if (ACT == 1) v = fmaxf(v, 0.f);
            if (ACT == 2) v = (v >= 0.f) ? v : alpha * v;
            C[(size_t)row * M + col] = v;
        }
    }
}

// ---------------- propagation: H = relu(A_g @ T_g + b), per graph ----------------
__global__ void prop_kernel(const float* __restrict__ A, const float* __restrict__ T,
                            const float* __restrict__ bias, float* __restrict__ out, int F) {
    __shared__ float sA[1024];
    __shared__ float sT[32 * 312];
    int g = blockIdx.x;
    const float* Ag = A + g * 1024;
    const float* Tg = T + (size_t)g * 32 * F;
    for (int i = threadIdx.x; i < 1024; i += 256) sA[i] = Ag[i];
    int tot = 32 * F;
    for (int i = threadIdx.x; i < tot; i += 256) sT[i] = Tg[i];
    __syncthreads();
    for (int idx = threadIdx.x; idx < tot; idx += 256) {
        int r = idx / F, f = idx - r * F;
        float acc = bias[f];
        const float* Ar = sA + r * 32;
#pragma unroll
        for (int c = 0; c < 32; c++) acc = fmaf(Ar[c], sT[c * F + f], acc);
        out[(size_t)(g * 32 + r) * F + f] = fmaxf(acc, 0.f);
    }
}

// ---------------- global max pool over 32 nodes per graph ----------------
__global__ void pool_kernel(const float* __restrict__ H, float* __restrict__ out, int F) {
    int g = blockIdx.x, f = threadIdx.x;
    if (f >= F) return;
    const float* Hg = H + (size_t)g * 32 * F;
    float m = -3.4e38f;
#pragma unroll
    for (int r = 0; r < 32; r++) m = fmaxf(m, Hg[r * F + f]);
    out[g * F + f] = m;
}

// ---------------- concat [g1,g2,c] + L2 normalize row ----------------
__global__ void catnorm_kernel(const float* __restrict__ g1, const float* __restrict__ g2,
                               const float* __restrict__ c, float* __restrict__ xc) {
    int g = blockIdx.x, t = threadIdx.x;   // 128 threads
    float v0 = g1[g * 128 + t], v1 = g2[g * 128 + t], v2 = c[g * 128 + t];
    float ps = v0 * v0 + v1 * v1 + v2 * v2;
    __shared__ float red[4];
#pragma unroll
    for (int o = 16; o; o >>= 1) ps += __shfl_xor_sync(0xffffffffu, ps, o);
    if ((t & 31) == 0) red[t >> 5] = ps;
    __syncthreads();
    float tot = red[0] + red[1] + red[2] + red[3];
    float inv = 1.f / fmaxf(sqrtf(tot), 1e-12f);
    xc[g * 384 + t]       = v0 * inv;
    xc[g * 384 + 128 + t] = v1 * inv;
    xc[g * 384 + 256 + t] = v2 * inv;
}

// ---------------- final: sigmoid(x @ Wo + bo), one warp per row ----------------
__global__ void final_kernel(const float* __restrict__ x, const float* __restrict__ Wo,
                             const float* __restrict__ bo, float* __restrict__ out) {
    int w = (blockIdx.x * blockDim.x + threadIdx.x) >> 5;
    int lane = threadIdx.x & 31;
    if (w >= NG) return;
    float acc = 0.f;
#pragma unroll
    for (int k = lane; k < 128; k += 32) acc = fmaf(x[w * 128 + k], Wo[k], acc);
#pragma unroll
    for (int o = 16; o; o >>= 1) acc += __shfl_xor_sync(0xffffffffu, acc, o);
    if (lane == 0) out[w] = 1.f / (1.f + expf(-(acc + bo[0])));
}

// ---------------- host side ----------------
static void gemm_launch(const float* X, const float* W, const float* bias, float* C,
                        int N, int K, int M, int act, const float* pa) {
    dim3 grid((M + BN - 1) / BN, (N + BM - 1) / BM);
    if (act == 0)      gemm_kernel<0><<<grid, 256>>>(X, W, bias, C, N, K, M, nullptr);
    else if (act == 1) gemm_kernel<1><<<grid, 256>>>(X, W, bias, C, N, K, M, nullptr);
    else               gemm_kernel<2><<<grid, 256>>>(X, W, bias, C, N, K, M, pa);
}

extern "C" void kernel_launch(void* const* d_in, const int* in_sizes, int n_in,
                              void* d_out, int out_size) {
    const float* x1   = (const float*)d_in[0];
    const int*   ei1  = (const int*)d_in[1];
    const float* x2   = (const float*)d_in[2];
    const int*   ei2  = (const int*)d_in[3];
    const float* cell = (const float*)d_in[4];
    // d_in[5], d_in[6]: batch vectors (implied by node index; unused)
    const float* W1  = (const float*)d_in[7],  *b1  = (const float*)d_in[8];
    const float* W2  = (const float*)d_in[9],  *b2  = (const float*)d_in[10];
    const float* W3  = (const float*)d_in[11], *b3  = (const float*)d_in[12];
    const float* Wg1 = (const float*)d_in[13], *bg1 = (const float*)d_in[14];
    const float* Wg2 = (const float*)d_in[15], *bg2 = (const float*)d_in[16];
    const float* Wr1 = (const float*)d_in[17], *br1 = (const float*)d_in[18];
    const float* Wr2 = (const float*)d_in[19], *br2 = (const float*)d_in[20];
    const float* Wr3 = (const float*)d_in[21], *br3 = (const float*)d_in[22];
    const float* Wf1 = (const float*)d_in[23], *bf1 = (const float*)d_in[24];
    const float* Wf2 = (const float*)d_in[25], *bf2 = (const float*)d_in[26];
    const float* Wo  = (const float*)d_in[27], *bo  = (const float*)d_in[28];
    const float* pa  = (const float*)d_in[29];
    float* out = (float*)d_out;

    float *A, *bufA, *bufB, *pool, *t512, *t256, *G1, *G2, *Cl, *XC;
    cudaGetSymbolAddress((void**)&A,    g_A);
    cudaGetSymbolAddress((void**)&bufA, g_bufA);
    cudaGetSymbolAddress((void**)&bufB, g_bufB);
    cudaGetSymbolAddress((void**)&pool, g_pool);
    cudaGetSymbolAddress((void**)&t512, g_t512);
    cudaGetSymbolAddress((void**)&t256, g_t256);
    cudaGetSymbolAddress((void**)&G1,   g_g1);
    cudaGetSymbolAddress((void**)&G2,   g_g2);
    cudaGetSymbolAddress((void**)&Cl,   g_cell);
    cudaGetSymbolAddress((void**)&XC,   g_xc);

    for (int d = 0; d < 2; d++) {
        const float* x  = d ? x2 : x1;
        const int*   ei = d ? ei2 : ei1;
        float*       G  = d ? G2 : G1;
        build_A_kernel<<<NG, 128>>>(ei, A);
        // layer 1: relu(A @ (x W1) + b1)
        gemm_launch(x, W1, nullptr, bufA, NN, 78, 78, 0, pa);
        prop_kernel<<<NG, 256>>>(A, bufA, b1, bufB, 78);
        // layer 2
        gemm_launch(bufB, W2, nullptr, bufA, NN, 78, 156, 0, pa);
        prop_kernel<<<NG, 256>>>(A, bufA, b2, bufB, 156);
        // layer 3
        gemm_launch(bufB, W3, nullptr, bufA, NN, 156, 312, 0, pa);
        prop_kernel<<<NG, 256>>>(A, bufA, b3, bufB, 312);
        // global max pool + FC head of drug branch
        pool_kernel<<<NG, 320>>>(bufB, pool, 312);
        gemm_launch(pool, Wg1, bg1, t512, NG, 312, 156, 1, pa);
        gemm_launch(t512, Wg2, bg2, G,    NG, 156, 128, 0, pa);
    }

    // cell-line MLP
    gemm_launch(cell, Wr1, br1, t512, NG, 1000, 512, 1, pa);
    gemm_launch(t512, Wr2, br2, t256, NG, 512,  256, 1, pa);
    gemm_launch(t256, Wr3, br3, Cl,   NG, 256,  128, 0, pa);

    // concat + L2 normalize + fused head
    catnorm_kernel<<<NG, 128>>>(G1, G2, Cl, XC);
    gemm_launch(XC,   Wf1, bf1, t512, NG, 384, 512, 2, pa);
    gemm_launch(t512, Wf2, bf2, t256, NG, 512, 128, 2, pa);
    final_kernel<<<NG / 8, 256>>>(t256, Wo, bo, out);
}